// round 6
// baseline (speedup 1.0000x reference)
#include <cuda_runtime.h>
#include <cuda_bf16.h>
#include <cstdint>

// ---------------------------------------------------------------------------
// Problem constants:  num_model=2, b=32, L=512, s=26, q=512
// Output: posterior (2,32,512,512) float32  followed by loglik (2,32) float32
// ---------------------------------------------------------------------------
#define NM 2
#define NB 32
#define LT 512
#define QQ 512
#define SS 26
#define POST_N (NM*NB*LT*QQ)   // 16777216

// ---------------------------------------------------------------------------
// Device scratch (static __device__ arrays: allocation-free at runtime)
// ---------------------------------------------------------------------------
__device__ float gA   [NM * QQ * QQ];       // softmax(transition_logits)         (2 MB)
__device__ float gAT  [NM * QQ * QQ];       // transpose of gA                    (2 MB)
__device__ float gBT  [NM * SS * QQ];       // softmax(emission) transposed [m][s][q]
__device__ float gLinit[NM * QQ];           // log_softmax(init_logits)
__device__ float gLogE[NM * NB * LT * QQ];  // log(em + eps)                      (64 MB)
__device__ float gBeta[NM * NB * LT * QQ];  // betas                              (64 MB)
__device__ float gLoglik[NM * NB];

// ---------------------------------------------------------------------------
// Block reductions over 512 threads, two values at once
// ---------------------------------------------------------------------------
__device__ __forceinline__ void blockMax2(float& a, float& b, float* s0, float* s1) {
    const unsigned full = 0xffffffffu;
    #pragma unroll
    for (int o = 16; o; o >>= 1) {
        a = fmaxf(a, __shfl_xor_sync(full, a, o));
        b = fmaxf(b, __shfl_xor_sync(full, b, o));
    }
    int w = threadIdx.x >> 5, l = threadIdx.x & 31;
    if (l == 0) { s0[w] = a; s1[w] = b; }
    __syncthreads();
    if (w == 0) {
        float x = (l < 16) ? s0[l] : -3.4e38f;
        float y = (l < 16) ? s1[l] : -3.4e38f;
        #pragma unroll
        for (int o = 8; o; o >>= 1) {
            x = fmaxf(x, __shfl_xor_sync(full, x, o));
            y = fmaxf(y, __shfl_xor_sync(full, y, o));
        }
        if (l == 0) { s0[0] = x; s1[0] = y; }
    }
    __syncthreads();
    a = s0[0]; b = s1[0];
    __syncthreads();   // protect scratch for next call
}

__device__ __forceinline__ void blockSum2(float& a, float& b, float* s0, float* s1) {
    const unsigned full = 0xffffffffu;
    #pragma unroll
    for (int o = 16; o; o >>= 1) {
        a += __shfl_xor_sync(full, a, o);
        b += __shfl_xor_sync(full, b, o);
    }
    int w = threadIdx.x >> 5, l = threadIdx.x & 31;
    if (l == 0) { s0[w] = a; s1[w] = b; }
    __syncthreads();
    if (w == 0) {
        float x = (l < 16) ? s0[l] : 0.f;
        float y = (l < 16) ? s1[l] : 0.f;
        #pragma unroll
        for (int o = 8; o; o >>= 1) {
            x += __shfl_xor_sync(full, x, o);
            y += __shfl_xor_sync(full, y, o);
        }
        if (l == 0) { s0[0] = x; s1[0] = y; }
    }
    __syncthreads();
    a = s0[0]; b = s1[0];
    __syncthreads();
}

// ---------------------------------------------------------------------------
// Prep 1: transition softmax -> gA (prob space) and gAT (transpose)
// grid = NM*QQ blocks (row per block), 256 threads, 2 cols/thread
// ---------------------------------------------------------------------------
__global__ __launch_bounds__(256) void prep_trans_kernel(const float* __restrict__ tl) {
    __shared__ float red[256];
    int row = blockIdx.x;                // m*QQ + k
    int m = row >> 9, k = row & (QQ - 1);
    int tid = threadIdx.x;
    float x0 = tl[row * QQ + tid];
    float x1 = tl[row * QQ + tid + 256];
    red[tid] = fmaxf(x0, x1);
    __syncthreads();
    for (int s = 128; s; s >>= 1) { if (tid < s) red[tid] = fmaxf(red[tid], red[tid + s]); __syncthreads(); }
    float M = red[0];
    __syncthreads();
    float e0 = __expf(x0 - M), e1 = __expf(x1 - M);
    red[tid] = e0 + e1;
    __syncthreads();
    for (int s = 128; s; s >>= 1) { if (tid < s) red[tid] += red[tid + s]; __syncthreads(); }
    float inv = 1.f / red[0];
    float p0 = e0 * inv, p1 = e1 * inv;
    gA[row * QQ + tid]       = p0;
    gA[row * QQ + tid + 256] = p1;
    size_t base = (size_t)m * QQ * QQ;
    gAT[base + (size_t)tid * QQ + k]         = p0;
    gAT[base + (size_t)(tid + 256) * QQ + k] = p1;
}

// ---------------------------------------------------------------------------
// Prep 2: init log_softmax -> gLinit.  grid = NM, 256 threads, 2 per thread
// ---------------------------------------------------------------------------
__global__ __launch_bounds__(256) void prep_init_kernel(const float* __restrict__ il) {
    __shared__ float red[256];
    int row = blockIdx.x;     // model
    int tid = threadIdx.x;
    float x0 = il[row * QQ + tid];
    float x1 = il[row * QQ + tid + 256];
    red[tid] = fmaxf(x0, x1);
    __syncthreads();
    for (int s = 128; s; s >>= 1) { if (tid < s) red[tid] = fmaxf(red[tid], red[tid + s]); __syncthreads(); }
    float M = red[0];
    __syncthreads();
    float e0 = __expf(x0 - M), e1 = __expf(x1 - M);
    red[tid] = e0 + e1;
    __syncthreads();
    for (int s = 128; s; s >>= 1) { if (tid < s) red[tid] += red[tid + s]; __syncthreads(); }
    float ls = __logf(red[0]);
    gLinit[row * QQ + tid]       = x0 - M - ls;
    gLinit[row * QQ + tid + 256] = x1 - M - ls;
}

// ---------------------------------------------------------------------------
// Prep 3: emission softmax -> gBT[m][s][q].  1 warp per (m,q) row of 26.
// grid = 128, block = 256 (8 warps) -> 1024 rows
// ---------------------------------------------------------------------------
__global__ __launch_bounds__(256) void prep_emis_kernel(const float* __restrict__ el) {
    const unsigned full = 0xffffffffu;
    int w = threadIdx.x >> 5, l = threadIdx.x & 31;
    int row = blockIdx.x * 8 + w;        // 0..1023 = m*QQ + q
    int m = row >> 9, q = row & (QQ - 1);
    float v = (l < SS) ? el[row * SS + l] : -3.4e38f;
    float M = v;
    #pragma unroll
    for (int o = 16; o; o >>= 1) M = fmaxf(M, __shfl_xor_sync(full, M, o));
    float e = (l < SS) ? __expf(v - M) : 0.f;
    float s = e;
    #pragma unroll
    for (int o = 16; o; o >>= 1) s += __shfl_xor_sync(full, s, o);
    if (l < SS) gBT[(size_t)m * SS * QQ + (size_t)l * QQ + q] = e / s;
}

// ---------------------------------------------------------------------------
// Prep 4: logE[m,b,l,q] = log(sum_s inputs[m,b,l,s] * B[m,q,s] + eps)
// grid = NM*NB*(LT/8) = 4096 blocks, block = 512 (q per thread),
// B column held in 26 registers across the 8 l's.
// ---------------------------------------------------------------------------
__global__ __launch_bounds__(512) void prep_logE_kernel(const float* __restrict__ inp) {
    __shared__ float sIn[SS];
    int bx = blockIdx.x;
    int lt = bx & 63;          // l-tile of 8
    int mb = bx >> 6;          // m*NB + b
    int m  = mb >> 5;
    int q  = threadIdx.x;
    float breg[SS];
    const float* bt = gBT + (size_t)m * SS * QQ;
    #pragma unroll
    for (int s = 0; s < SS; s++) breg[s] = bt[s * QQ + q];
    const float* ip = inp + ((size_t)mb * LT + (size_t)lt * 8) * SS;
    float* op = gLogE + ((size_t)mb * LT + (size_t)lt * 8) * QQ;
    for (int l = 0; l < 8; l++) {
        __syncthreads();
        if (q < SS) sIn[q] = ip[l * SS + q];
        __syncthreads();
        float em = 0.f;
        #pragma unroll
        for (int s = 0; s < SS; s++) em += breg[s] * sIn[s];
        op[l * QQ + q] = __logf(em + 1e-16f);
    }
}

// ---------------------------------------------------------------------------
// Main scan: grid = 64 CTAs, block = 512.
//   bx&1: 0=forward, 1=backward.  bx>>1 = (m, chain-pair): 2 chains per CTA.
// Forward writes alpha directly into d_out posterior slots; backward writes
// beta to gBeta.  Each step: prob-space matvec vs gA (fwd) / gAT (bwd),
// with per-step max shifting.  A element loaded once, used for both chains.
// Thread org: kp = tid>>7 (k-slice of 128), j4 = tid&127 (4 columns, float4).
// ---------------------------------------------------------------------------
__global__ __launch_bounds__(512) void hmm_scan_kernel(float* __restrict__ out) {
    __shared__ float se0[QQ], se1[QQ];       // exp(state - M), per chain
    __shared__ float sY[4 * QQ * 2];         // k-slice partials, 2 chains (16 KB)
    __shared__ float sR0[16], sR1[16];

    int bx  = blockIdx.x;
    int dir = bx & 1;                 // 0 fwd, 1 bwd
    int cp  = bx >> 1;                // 0..31
    int m   = cp >> 4;
    int bp  = cp & 15;
    int b0  = 2 * bp, b1 = 2 * bp + 1;

    const float4* Mat4 = (const float4*)((dir == 0 ? gA : gAT) + (size_t)m * QQ * QQ);
    const float* le0 = gLogE + (size_t)((m * NB + b0) * LT) * QQ;
    const float* le1 = gLogE + (size_t)((m * NB + b1) * LT) * QQ;
    float* st0 = (dir == 0 ? out : gBeta) + (size_t)((m * NB + b0) * LT) * QQ;
    float* st1 = (dir == 0 ? out : gBeta) + (size_t)((m * NB + b1) * LT) * QQ;

    int tid = threadIdx.x;
    int kp  = tid >> 7;               // 0..3
    int j4  = tid & 127;              // column group (4 cols)
    int kbase = kp * 128;

    // ---- init (t=0 for fwd, t=LT-1 for bwd) ----
    float g0, g1;
    {
        int j = tid;
        if (dir == 0) {
            float li = gLinit[m * QQ + j];
            float v0 = li + le0[j];
            float v1 = li + le1[j];
            st0[j] = v0; st1[j] = v1;
            g0 = v0; g1 = v1;
        } else {
            st0[(size_t)(LT - 1) * QQ + j] = 0.f;
            st1[(size_t)(LT - 1) * QQ + j] = 0.f;
            g0 = le0[(LT - 1) * QQ + j];
            g1 = le1[(LT - 1) * QQ + j];
        }
    }
    float M0 = g0, M1 = g1;
    blockMax2(M0, M1, sR0, sR1);
    se0[tid] = __expf(g0 - M0);
    se1[tid] = __expf(g1 - M1);
    __syncthreads();

    // ---- 511 recurrence steps ----
    for (int i = 1; i < LT; i++) {
        int t = (dir == 0) ? i : (LT - 1 - i);

        // matvec partial over this thread's k-slice, 4 columns, 2 chains
        float4 a0 = make_float4(0.f, 0.f, 0.f, 0.f);
        float4 a1 = make_float4(0.f, 0.f, 0.f, 0.f);
        const float4* pA  = Mat4 + (size_t)kbase * 128 + j4;
        const float4* pe0 = (const float4*)(se0 + kbase);
        const float4* pe1 = (const float4*)(se1 + kbase);
        #pragma unroll 8
        for (int kk4 = 0; kk4 < 32; kk4++) {
            float4 e0v = pe0[kk4];
            float4 e1v = pe1[kk4];
            float4 av;
            av = pA[0];
            a0.x += e0v.x * av.x; a0.y += e0v.x * av.y; a0.z += e0v.x * av.z; a0.w += e0v.x * av.w;
            a1.x += e1v.x * av.x; a1.y += e1v.x * av.y; a1.z += e1v.x * av.z; a1.w += e1v.x * av.w;
            av = pA[128];
            a0.x += e0v.y * av.x; a0.y += e0v.y * av.y; a0.z += e0v.y * av.z; a0.w += e0v.y * av.w;
            a1.x += e1v.y * av.x; a1.y += e1v.y * av.y; a1.z += e1v.y * av.z; a1.w += e1v.y * av.w;
            av = pA[256];
            a0.x += e0v.z * av.x; a0.y += e0v.z * av.y; a0.z += e0v.z * av.z; a0.w += e0v.z * av.w;
            a1.x += e1v.z * av.x; a1.y += e1v.z * av.y; a1.z += e1v.z * av.z; a1.w += e1v.z * av.w;
            av = pA[384];
            a0.x += e0v.w * av.x; a0.y += e0v.w * av.y; a0.z += e0v.w * av.z; a0.w += e0v.w * av.w;
            a1.x += e1v.w * av.x; a1.y += e1v.w * av.y; a1.z += e1v.w * av.z; a1.w += e1v.w * av.w;
            pA += 512;
        }
        ((float4*)sY)[kp * 128 + j4]         = a0;
        ((float4*)(sY + 2048))[kp * 128 + j4] = a1;
        __syncthreads();

        // cross-kp reduction + finish (thread tid -> column j = tid)
        int j = tid;
        float y0 = sY[j] + sY[512 + j] + sY[1024 + j] + sY[1536 + j];
        float y1 = sY[2048 + j] + sY[2560 + j] + sY[3072 + j] + sY[3584 + j];
        float lE0 = le0[(size_t)t * QQ + j];
        float lE1 = le1[(size_t)t * QQ + j];
        float v0, v1;
        if (dir == 0) {
            v0 = M0 + __logf(y0) + lE0;
            v1 = M1 + __logf(y1) + lE1;
            g0 = v0; g1 = v1;
        } else {
            v0 = M0 + __logf(y0);
            v1 = M1 + __logf(y1);
            g0 = v0 + lE0; g1 = v1 + lE1;
        }
        st0[(size_t)t * QQ + j] = v0;
        st1[(size_t)t * QQ + j] = v1;

        M0 = g0; M1 = g1;
        blockMax2(M0, M1, sR0, sR1);          // internal syncs also fence sY reads
        se0[tid] = __expf(g0 - M0);
        se1[tid] = __expf(g1 - M1);
        __syncthreads();
    }

    // ---- forward CTAs: loglik = M + log(sum exp(alpha_last - M)) ----
    if (dir == 0) {
        float s0 = se0[tid], s1 = se1[tid];
        blockSum2(s0, s1, sR0, sR1);
        if (tid == 0) {
            gLoglik[m * NB + b0] = M0 + __logf(s0);
            gLoglik[m * NB + b1] = M1 + __logf(s1);
        }
    }
}

// ---------------------------------------------------------------------------
// Epilogue: posterior = alpha(already in out) + beta - loglik; append loglik.
// grid = 16384, block = 256, float4 per thread.
// ---------------------------------------------------------------------------
__global__ __launch_bounds__(256) void epilogue_kernel(float* __restrict__ out, int out_size) {
    size_t i4 = (size_t)blockIdx.x * 256 + threadIdx.x;   // 0..4194303
    float4 o  = ((const float4*)out)[i4];
    float4 bb = ((const float4*)gBeta)[i4];
    int chain = (int)(i4 >> 16);                          // (i4*4) / (LT*QQ)
    float ll = gLoglik[chain];
    o.x += bb.x - ll;
    o.y += bb.y - ll;
    o.z += bb.z - ll;
    o.w += bb.w - ll;
    ((float4*)out)[i4] = o;
    if (blockIdx.x == 0 && threadIdx.x < NM * NB && out_size >= POST_N + NM * NB)
        out[POST_N + threadIdx.x] = gLoglik[threadIdx.x];
}

// ---------------------------------------------------------------------------
// Launch
// ---------------------------------------------------------------------------
extern "C" void kernel_launch(void* const* d_in, const int* in_sizes, int n_in,
                              void* d_out, int out_size) {
    const float* inputs = (const float*)d_in[0];   // (2,32,512,26)
    const float* tl     = (const float*)d_in[1];   // (2,512,512)
    const float* el     = (const float*)d_in[2];   // (2,512,26)
    const float* il     = (const float*)d_in[3];   // (2,512)
    float* out = (float*)d_out;

    prep_trans_kernel<<<NM * QQ, 256>>>(tl);
    prep_emis_kernel<<<128, 256>>>(el);
    prep_init_kernel<<<NM, 256>>>(il);
    prep_logE_kernel<<<NM * NB * (LT / 8), 512>>>(inputs);
    hmm_scan_kernel<<<64, 512>>>(out);
    epilogue_kernel<<<POST_N / 4 / 256, 256>>>(out, out_size);
}

// round 7
// speedup vs baseline: 1.0311x; 1.0311x over previous
#include <cuda_runtime.h>
#include <cuda_bf16.h>
#include <cstdint>

// ---------------------------------------------------------------------------
// Problem constants:  num_model=2, b=32, L=512, s=26, q=512
// Output: posterior (2,32,512,512) float32  followed by loglik (2,32) float32
// ---------------------------------------------------------------------------
#define NM 2
#define NB 32
#define LT 512
#define QQ 512
#define SS 26
#define POST_N (NM*NB*LT*QQ)   // 16777216

#define RANKS 8        // CTAs per cluster
#define CCH 8          // chains per team
#define EBS 516        // ebuf per-chain stride in floats (padded: conflict-free)
#define EBUF_F (CCH*EBS)   // 4128 floats per buffer
#define SYS 68         // sY row stride in floats

// smem float offsets (dynamic smem, one block)
#define OFF_A     0        // A slice: 512*64 = 32768 floats (128KB)
#define OFF_EB    32768    // e buffers: 2 * 4128 = 8256 floats
#define OFF_SY    41024    // partials: 64 * 68 = 4352 floats
#define OFF_WRED  45376    // 16 floats
#define OFF_MLS   45392    // 8 floats (local chain maxes)
#define OFF_MR    45400    // 2 * 64 floats (per-rank maxes, double buffered)
#define SMEM_FLOATS 45528
#define SMEM_BYTES (SMEM_FLOATS*4)   // 182112 bytes

// ---------------------------------------------------------------------------
// Device scratch (static __device__ arrays: allocation-free at runtime)
// ---------------------------------------------------------------------------
__device__ float gA    [NM * QQ * QQ];       // softmax(transition_logits)
__device__ float gAT   [NM * QQ * QQ];       // transpose of gA
__device__ float gBT   [NM * SS * QQ];       // softmax(emission) transposed [m][s][q]
__device__ float gLinit[NM * QQ];            // log_softmax(init_logits)
__device__ float gLogE [NM * NB * LT * QQ];  // log(em + eps)
__device__ float gBeta [NM * NB * LT * QQ];  // betas
__device__ float gLoglik[NM * NB];
__device__ float gLLsum [8 * RANKS * CCH];   // fwd per-rank partial sums
__device__ float gLLmaxR[8 * RANKS * CCH];   // fwd per-rank local maxes

// ---------------------------------------------------------------------------
// PTX helpers
// ---------------------------------------------------------------------------
__device__ __forceinline__ uint32_t smem_u32(const void* p) {
    uint32_t a;
    asm("{ .reg .u64 t; cvta.to.shared.u64 t, %1; cvt.u32.u64 %0, t; }"
        : "=r"(a) : "l"(p));
    return a;
}
__device__ __forceinline__ uint32_t ctarank() {
    uint32_t r; asm("mov.u32 %0, %%cluster_ctarank;" : "=r"(r)); return r;
}
__device__ __forceinline__ void cluster_sync_all() {
    asm volatile("barrier.cluster.arrive.aligned;" ::: "memory");
    asm volatile("barrier.cluster.wait.aligned;" ::: "memory");
}
__device__ __forceinline__ void st_cluster_f32(uint32_t laddr, uint32_t peer, float v) {
    uint32_t ra;
    asm volatile("mapa.shared::cluster.u32 %0, %1, %2;" : "=r"(ra) : "r"(laddr), "r"(peer));
    asm volatile("st.shared::cluster.u32 [%0], %1;" :: "r"(ra), "r"(__float_as_uint(v)) : "memory");
}

#define FMA4(acc, s, v) { acc.x = fmaf((s),(v).x,acc.x); acc.y = fmaf((s),(v).y,acc.y); \
                          acc.z = fmaf((s),(v).z,acc.z); acc.w = fmaf((s),(v).w,acc.w); }

// ---------------------------------------------------------------------------
// Prep 1: transition softmax -> gA (prob space) and gAT (transpose)
// ---------------------------------------------------------------------------
__global__ __launch_bounds__(256) void prep_trans_kernel(const float* __restrict__ tl) {
    __shared__ float red[256];
    int row = blockIdx.x;                // m*QQ + k
    int m = row >> 9, k = row & (QQ - 1);
    int tid = threadIdx.x;
    float x0 = tl[row * QQ + tid];
    float x1 = tl[row * QQ + tid + 256];
    red[tid] = fmaxf(x0, x1);
    __syncthreads();
    for (int s = 128; s; s >>= 1) { if (tid < s) red[tid] = fmaxf(red[tid], red[tid + s]); __syncthreads(); }
    float M = red[0];
    __syncthreads();
    float e0 = __expf(x0 - M), e1 = __expf(x1 - M);
    red[tid] = e0 + e1;
    __syncthreads();
    for (int s = 128; s; s >>= 1) { if (tid < s) red[tid] += red[tid + s]; __syncthreads(); }
    float inv = 1.f / red[0];
    float p0 = e0 * inv, p1 = e1 * inv;
    gA[row * QQ + tid]       = p0;
    gA[row * QQ + tid + 256] = p1;
    size_t base = (size_t)m * QQ * QQ;
    gAT[base + (size_t)tid * QQ + k]         = p0;
    gAT[base + (size_t)(tid + 256) * QQ + k] = p1;
}

// ---------------------------------------------------------------------------
// Prep 2: init log_softmax -> gLinit
// ---------------------------------------------------------------------------
__global__ __launch_bounds__(256) void prep_init_kernel(const float* __restrict__ il) {
    __shared__ float red[256];
    int row = blockIdx.x;
    int tid = threadIdx.x;
    float x0 = il[row * QQ + tid];
    float x1 = il[row * QQ + tid + 256];
    red[tid] = fmaxf(x0, x1);
    __syncthreads();
    for (int s = 128; s; s >>= 1) { if (tid < s) red[tid] = fmaxf(red[tid], red[tid + s]); __syncthreads(); }
    float M = red[0];
    __syncthreads();
    float e0 = __expf(x0 - M), e1 = __expf(x1 - M);
    red[tid] = e0 + e1;
    __syncthreads();
    for (int s = 128; s; s >>= 1) { if (tid < s) red[tid] += red[tid + s]; __syncthreads(); }
    float ls = __logf(red[0]);
    gLinit[row * QQ + tid]       = x0 - M - ls;
    gLinit[row * QQ + tid + 256] = x1 - M - ls;
}

// ---------------------------------------------------------------------------
// Prep 3: emission softmax -> gBT[m][s][q]
// ---------------------------------------------------------------------------
__global__ __launch_bounds__(256) void prep_emis_kernel(const float* __restrict__ el) {
    const unsigned full = 0xffffffffu;
    int w = threadIdx.x >> 5, l = threadIdx.x & 31;
    int row = blockIdx.x * 8 + w;        // m*QQ + q
    int m = row >> 9, q = row & (QQ - 1);
    float v = (l < SS) ? el[row * SS + l] : -3.4e38f;
    float M = v;
    #pragma unroll
    for (int o = 16; o; o >>= 1) M = fmaxf(M, __shfl_xor_sync(full, M, o));
    float e = (l < SS) ? __expf(v - M) : 0.f;
    float s = e;
    #pragma unroll
    for (int o = 16; o; o >>= 1) s += __shfl_xor_sync(full, s, o);
    if (l < SS) gBT[(size_t)m * SS * QQ + (size_t)l * QQ + q] = e / s;
}

// ---------------------------------------------------------------------------
// Prep 4: logE[m,b,l,q] = log(sum_s inputs[m,b,l,s] * B[m,q,s] + eps)
// ---------------------------------------------------------------------------
__global__ __launch_bounds__(512) void prep_logE_kernel(const float* __restrict__ inp) {
    __shared__ float sIn[SS];
    int bx = blockIdx.x;
    int lt = bx & 63;
    int mb = bx >> 6;
    int m  = mb >> 5;
    int q  = threadIdx.x;
    float breg[SS];
    const float* bt = gBT + (size_t)m * SS * QQ;
    #pragma unroll
    for (int s = 0; s < SS; s++) breg[s] = bt[s * QQ + q];
    const float* ip = inp + ((size_t)mb * LT + (size_t)lt * 8) * SS;
    float* op = gLogE + ((size_t)mb * LT + (size_t)lt * 8) * QQ;
    for (int l = 0; l < 8; l++) {
        __syncthreads();
        if (q < SS) sIn[q] = ip[l * SS + q];
        __syncthreads();
        float em = 0.f;
        #pragma unroll
        for (int s = 0; s < SS; s++) em += breg[s] * sIn[s];
        op[l * QQ + q] = __logf(em + 1e-16f);
    }
}

// ---------------------------------------------------------------------------
// Scan tail: local per-chain max (rank-local shift), broadcast e + local max
// to all peers into buffer `buf`.  One cluster sync.  Returns this thread's e.
// ---------------------------------------------------------------------------
__device__ __forceinline__ float scan_tail(float g, int buf, int tid, int c, int eoff,
                                           uint32_t myrank, float* eb, float* wred,
                                           float* MlS, float* Mr) {
    const unsigned full = 0xffffffffu;
    float wm = g;
    #pragma unroll
    for (int o = 16; o; o >>= 1) wm = fmaxf(wm, __shfl_xor_sync(full, wm, o));
    if ((tid & 31) == 0) wred[tid >> 5] = wm;
    __syncthreads();
    if (tid < 8) {
        float lm = fmaxf(wred[2 * tid], wred[2 * tid + 1]);
        MlS[tid] = lm;
        float* dst = Mr + buf * 64 + (int)myrank * 8 + tid;
        *dst = lm;
        uint32_t la = smem_u32(dst);
        #pragma unroll
        for (int p = 0; p < RANKS; p++)
            if ((uint32_t)p != myrank) st_cluster_f32(la, (uint32_t)p, lm);
    }
    __syncthreads();
    float e = __expf(g - MlS[c]);
    float* d2 = eb + buf * EBUF_F + eoff;
    *d2 = e;
    uint32_t la2 = smem_u32(d2);
    #pragma unroll
    for (int p = 0; p < RANKS; p++)
        if ((uint32_t)p != myrank) st_cluster_f32(la2, (uint32_t)p, e);
    cluster_sync_all();
    return e;
}

// ---------------------------------------------------------------------------
// Main scan: 16 clusters of 8 CTAs (2 models x 2 dirs x 4 chain-groups).
// Each CTA: resident 512x64 A-slice in SMEM, computes its 64 output columns
// for 8 chains; e-state broadcast over DSMEM each step, 1 cluster sync/step.
// ---------------------------------------------------------------------------
__global__ void __launch_bounds__(512, 1) __cluster_dims__(RANKS, 1, 1)
hmm_scan_cluster(float* __restrict__ out) {
    extern __shared__ float sm[];
    float* sA   = sm + OFF_A;
    float* eb   = sm + OFF_EB;
    float* sY   = sm + OFF_SY;
    float* wred = sm + OFF_WRED;
    float* MlS  = sm + OFF_MLS;
    float* Mr   = sm + OFF_MR;

    int tid = threadIdx.x;
    uint32_t r = ctarank();
    int cid = blockIdx.x >> 3;
    int m   = cid >> 3;
    int dir = (cid >> 2) & 1;
    int grp = cid & 3;

    // load resident A slice: columns [r*64, r*64+64) of gA/gAT[m]
    const float* Asrc = (dir == 0 ? gA : gAT) + (size_t)m * QQ * QQ + (size_t)r * 64;
    for (int idx = tid; idx < QQ * 16; idx += 512) {
        int k = idx >> 4, c4 = idx & 15;
        ((float4*)sA)[k * 16 + c4] = ((const float4*)(Asrc + (size_t)k * QQ))[c4];
    }

    // output-phase mapping: thread -> (chain c, column col)
    int c = tid >> 6, col = tid & 63;
    // matvec-phase mapping: thread -> (k-slice kp, colgroup cg, chainpair cp)
    int cp = tid & 3, cg = (tid >> 2) & 15, kp = tid >> 6;

    int b  = grp * 8 + c;
    const float* le = gLogE + (size_t)(m * NB + b) * LT * QQ;
    float* stp = (dir == 0 ? out : gBeta) + (size_t)(m * NB + b) * LT * QQ;
    int jg   = (int)r * 64 + col;          // global column owned by this thread
    int eoff = c * EBS + jg;               // slot in e-buffer

    const float4* sA4 = (const float4*)sA;
    float4* sY4 = (float4*)sY;

    __syncthreads();
    cluster_sync_all();    // all peers resident before first DSMEM write

    // ---- init state ----
    float g;
    if (dir == 0) {
        g = gLinit[m * QQ + jg] + le[jg];
        stp[jg] = g;
    } else {
        stp[(size_t)(LT - 1) * QQ + jg] = 0.f;
        g = le[(size_t)(LT - 1) * QQ + jg];
    }

    int buf = 0;
    float e = scan_tail(g, buf, tid, c, eoff, r, eb, wred, MlS, Mr);

    // ---- 511 recurrence steps ----
    for (int i = 1; i < LT; i++) {
        int t = dir ? (LT - 1 - i) : i;

        // matvec: partial over k-slice [kp*64, kp*64+64), 4 cols, 2 chains
        const float* ecur = eb + buf * EBUF_F;
        const float4* e0p = (const float4*)(ecur + (2 * cp) * EBS) + kp * 16;
        const float4* e1p = (const float4*)(ecur + (2 * cp + 1) * EBS) + kp * 16;
        const float4* pA  = sA4 + kp * 64 * 16 + cg;
        float4 acc0 = make_float4(0.f, 0.f, 0.f, 0.f);
        float4 acc1 = make_float4(0.f, 0.f, 0.f, 0.f);
        #pragma unroll
        for (int k4 = 0; k4 < 16; k4++) {
            float4 e0 = e0p[k4], e1 = e1p[k4];
            float4 r0 = pA[0], r1 = pA[16], r2 = pA[32], r3 = pA[48];
            FMA4(acc0, e0.x, r0); FMA4(acc0, e0.y, r1); FMA4(acc0, e0.z, r2); FMA4(acc0, e0.w, r3);
            FMA4(acc1, e1.x, r0); FMA4(acc1, e1.y, r1); FMA4(acc1, e1.z, r2); FMA4(acc1, e1.w, r3);
            pA += 64;
        }
        sY4[(kp * 8 + 2 * cp) * 17 + cg]     = acc0;
        sY4[(kp * 8 + 2 * cp + 1) * 17 + cg] = acc1;
        __syncthreads();

        // weighted cross-rank reduce: k-slice kp == source rank kp, so
        // rescale each partial from that rank's local max to the global max.
        const float* mr = Mr + buf * 64;
        float Mv[8];
        #pragma unroll
        for (int rr = 0; rr < 8; rr++) Mv[rr] = mr[rr * 8 + c];
        float Mgl = Mv[0];
        #pragma unroll
        for (int rr = 1; rr < 8; rr++) Mgl = fmaxf(Mgl, Mv[rr]);
        float y = 0.f;
        #pragma unroll
        for (int rr = 0; rr < 8; rr++)
            y += __expf(Mv[rr] - Mgl) * sY[(rr * 8 + c) * SYS + col];

        float lE = le[(size_t)t * QQ + jg];
        float v, gn;
        if (dir == 0) { v = Mgl + __logf(y) + lE; gn = v; }
        else          { v = Mgl + __logf(y);      gn = v + lE; }
        stp[(size_t)t * QQ + jg] = v;
        g = gn;

        buf ^= 1;
        e = scan_tail(g, buf, tid, c, eoff, r, eb, wred, MlS, Mr);
    }

    // ---- forward teams: per-rank loglik partials (scale = final local max) ----
    if (dir == 0) {
        const unsigned full = 0xffffffffu;
        float ws = e;
        #pragma unroll
        for (int o = 16; o; o >>= 1) ws += __shfl_xor_sync(full, ws, o);
        if ((tid & 31) == 0) wred[tid >> 5] = ws;
        __syncthreads();
        if (tid < 8) {
            int team = m * 4 + grp;
            gLLsum [(team * 8 + (int)r) * 8 + tid] = wred[2 * tid] + wred[2 * tid + 1];
            gLLmaxR[(team * 8 + (int)r) * 8 + tid] = MlS[tid];
        }
    }
}

// ---------------------------------------------------------------------------
// Combine per-rank loglik partials: 64 threads, one per chain
// ---------------------------------------------------------------------------
__global__ void loglik_kernel() {
    int t = threadIdx.x;                // 0..63 = m*32 + b
    int mm = t >> 5, bb = t & 31;
    int team = mm * 4 + (bb >> 3), c = bb & 7;
    float Ms[8], Ss[8];
    float M = -3.4e38f;
    #pragma unroll
    for (int rr = 0; rr < 8; rr++) {
        Ms[rr] = gLLmaxR[(team * 8 + rr) * 8 + c];
        Ss[rr] = gLLsum [(team * 8 + rr) * 8 + c];
        M = fmaxf(M, Ms[rr]);
    }
    float s = 0.f;
    #pragma unroll
    for (int rr = 0; rr < 8; rr++) s += __expf(Ms[rr] - M) * Ss[rr];
    gLoglik[t] = M + __logf(s);
}

// ---------------------------------------------------------------------------
// Epilogue: posterior = alpha(in out) + beta - loglik; append loglik.
// ---------------------------------------------------------------------------
__global__ __launch_bounds__(256) void epilogue_kernel(float* __restrict__ out, int out_size) {
    size_t i4 = (size_t)blockIdx.x * 256 + threadIdx.x;
    float4 o  = ((const float4*)out)[i4];
    float4 bb = ((const float4*)gBeta)[i4];
    int chain = (int)(i4 >> 16);
    float ll = gLoglik[chain];
    o.x += bb.x - ll;
    o.y += bb.y - ll;
    o.z += bb.z - ll;
    o.w += bb.w - ll;
    ((float4*)out)[i4] = o;
    if (blockIdx.x == 0 && threadIdx.x < NM * NB && out_size >= POST_N + NM * NB)
        out[POST_N + threadIdx.x] = gLoglik[threadIdx.x];
}

// ---------------------------------------------------------------------------
// Launch
// ---------------------------------------------------------------------------
extern "C" void kernel_launch(void* const* d_in, const int* in_sizes, int n_in,
                              void* d_out, int out_size) {
    const float* inputs = (const float*)d_in[0];   // (2,32,512,26)
    const float* tl     = (const float*)d_in[1];   // (2,512,512)
    const float* el     = (const float*)d_in[2];   // (2,512,26)
    const float* il     = (const float*)d_in[3];   // (2,512)
    float* out = (float*)d_out;

    cudaFuncSetAttribute(hmm_scan_cluster,
                         cudaFuncAttributeMaxDynamicSharedMemorySize, SMEM_BYTES);

    prep_trans_kernel<<<NM * QQ, 256>>>(tl);
    prep_emis_kernel<<<128, 256>>>(el);
    prep_init_kernel<<<NM, 256>>>(il);
    prep_logE_kernel<<<NM * NB * (LT / 8), 512>>>(inputs);
    hmm_scan_cluster<<<16 * RANKS, 512, SMEM_BYTES>>>(out);
    loglik_kernel<<<1, 64>>>();
    epilogue_kernel<<<POST_N / 4 / 256, 256>>>(out, out_size);
}